// round 1
// baseline (speedup 1.0000x reference)
#include <cuda_runtime.h>

// Problem constants
#define B_  2
#define S_  2048
#define D_  2560
#define H_  32
#define HD_ 80
#define RD_ 32

constexpr int M_ROWS = B_ * S_;       // 4096
constexpr int QKV_N  = 3 * D_;        // 7680

// Scratch (no allocation allowed -> __device__ globals)
__device__ float g_qkv[(size_t)M_ROWS * QKV_N];   // ~126 MB
__device__ float g_ctx[(size_t)M_ROWS * D_];      // ~42 MB

// ---------------------------------------------------------------------------
// Packed fp32x2 FMA helpers (FFMA2 -- only reachable via PTX on sm_103a)
// ---------------------------------------------------------------------------
__device__ __forceinline__ unsigned long long pack2(float x) {
    unsigned long long r;
    asm("mov.b64 %0, {%1, %1};" : "=l"(r) : "f"(x));
    return r;
}
__device__ __forceinline__ void ffma2(unsigned long long& d,
                                      unsigned long long a,
                                      unsigned long long b) {
    asm("fma.rn.f32x2 %0, %1, %2, %0;" : "+l"(d) : "l"(a), "l"(b));
}
__device__ __forceinline__ float2 unpack2(unsigned long long v) {
    float2 r;
    asm("mov.b64 {%0, %1}, %2;" : "=f"(r.x), "=f"(r.y) : "l"(v));
    return r;
}

// ---------------------------------------------------------------------------
// NT GEMM with bias: C[M,N] = A[M,K] @ W[N,K]^T + bias[N]
// BM=BN=128, BK=16, 256 threads, 8x8 micro-tile, FFMA2 inner loop.
// M,N divisible by 128; K divisible by 16 (4096/7680/2560 all satisfy).
// ---------------------------------------------------------------------------
template<int BM, int BN, int BK>
__global__ __launch_bounds__(256, 2)
void sgemm_nt_bias(const float* __restrict__ A, const float* __restrict__ W,
                   const float* __restrict__ bias, float* __restrict__ C,
                   int M, int N, int K)
{
    __shared__ float As[BK][BM + 4];
    __shared__ float Bs[BK][BN + 4];

    const int tid = threadIdx.x;
    const int bm  = blockIdx.y * BM;
    const int bn  = blockIdx.x * BN;
    const int lr  = tid >> 2;          // 0..63 : row within half-tile
    const int lq  = (tid & 3) << 2;    // 0,4,8,12 : k offset
    const int tx  = tid & 15;
    const int ty  = tid >> 4;

    unsigned long long acc[8][4];
    #pragma unroll
    for (int i = 0; i < 8; ++i)
        #pragma unroll
        for (int j = 0; j < 4; ++j) acc[i][j] = 0ULL;

    const float* Aptr = A + (size_t)(bm + lr) * K + lq;
    const float* Wptr = W + (size_t)(bn + lr) * K + lq;

    for (int k0 = 0; k0 < K; k0 += BK) {
        #pragma unroll
        for (int hh = 0; hh < 2; ++hh) {
            const int row = lr + 64 * hh;
            float4 va = *(const float4*)(Aptr + (size_t)(64 * hh) * K + k0);
            As[lq + 0][row] = va.x; As[lq + 1][row] = va.y;
            As[lq + 2][row] = va.z; As[lq + 3][row] = va.w;
            float4 vb = *(const float4*)(Wptr + (size_t)(64 * hh) * K + k0);
            Bs[lq + 0][row] = vb.x; Bs[lq + 1][row] = vb.y;
            Bs[lq + 2][row] = vb.z; Bs[lq + 3][row] = vb.w;
        }
        __syncthreads();

        #pragma unroll
        for (int kk = 0; kk < BK; ++kk) {
            float4 a0 = *(const float4*)&As[kk][ty * 8];
            float4 a1 = *(const float4*)&As[kk][ty * 8 + 4];
            unsigned long long b2[4];
            #pragma unroll
            for (int j = 0; j < 4; ++j)
                b2[j] = *(const unsigned long long*)&Bs[kk][tx * 8 + 2 * j];
            unsigned long long a2[8];
            a2[0] = pack2(a0.x); a2[1] = pack2(a0.y);
            a2[2] = pack2(a0.z); a2[3] = pack2(a0.w);
            a2[4] = pack2(a1.x); a2[5] = pack2(a1.y);
            a2[6] = pack2(a1.z); a2[7] = pack2(a1.w);
            #pragma unroll
            for (int i = 0; i < 8; ++i)
                #pragma unroll
                for (int j = 0; j < 4; ++j)
                    ffma2(acc[i][j], a2[i], b2[j]);
        }
        __syncthreads();
    }

    // Epilogue: bias + store
    float bv[8];
    #pragma unroll
    for (int j = 0; j < 8; ++j) bv[j] = bias[bn + tx * 8 + j];

    #pragma unroll
    for (int i = 0; i < 8; ++i) {
        const int row = bm + ty * 8 + i;
        float out[8];
        #pragma unroll
        for (int j = 0; j < 4; ++j) {
            float2 v = unpack2(acc[i][j]);
            out[2 * j + 0] = v.x + bv[2 * j + 0];
            out[2 * j + 1] = v.y + bv[2 * j + 1];
        }
        float4* cp = (float4*)&C[(size_t)row * N + bn + tx * 8];
        cp[0] = make_float4(out[0], out[1], out[2], out[3]);
        cp[1] = make_float4(out[4], out[5], out[6], out[7]);
    }
}

// ---------------------------------------------------------------------------
// RoPE (in-place on qkv, first RD dims of each q/k head)
// one thread per (b, s, part, h, i) with i in [0,16)
// ---------------------------------------------------------------------------
__global__ void rope_kernel(float* __restrict__ qkv)
{
    int idx = blockIdx.x * blockDim.x + threadIdx.x;
    const int total = B_ * S_ * 2 * H_ * (RD_ / 2);   // 4,194,304
    if (idx >= total) return;
    const int i    = idx & 15;  idx >>= 4;
    const int h    = idx & 31;  idx >>= 5;
    const int part = idx & 1;   idx >>= 1;
    const int s    = idx & (S_ - 1); idx >>= 11;
    const int b    = idx;

    // inv_freq = 10000^(-2i/32); compute in double, cos/sin in float (matches
    // the fp32 reference within ~1 ulp of its own angle rounding)
    const double inv = exp2(-(double)i * (13.287712379549449 / 16.0));
    const float ang  = (float)((double)s * inv);
    const float c  = cosf(ang);
    const float si = sinf(ang);

    const size_t base = ((size_t)(b * S_ + s)) * QKV_N + (size_t)part * D_ + h * HD_;
    const float t1 = qkv[base + i];
    const float t2 = qkv[base + 16 + i];
    qkv[base + i]      = t1 * c  - t2 * si;
    qkv[base + 16 + i] = t1 * si + t2 * c;
}

// ---------------------------------------------------------------------------
// Causal flash attention, fp32.
// grid: (S/64, H, B), block 256 (8 warps x 8 query rows), key tiles of 64.
// smem: Qs/Ks/Vs [64][81] (pad->conflict-free) + Ps [64][64]
// ---------------------------------------------------------------------------
constexpr int ATTN_SMEM = (3 * 64 * 81 + 64 * 64) * 4;   // 78,592 B

__global__ __launch_bounds__(256, 2)
void attn_kernel(const float* __restrict__ qkv, float* __restrict__ ctx)
{
    extern __shared__ float sm[];
    float* Qs = sm;                 // 64*81
    float* Ks = Qs + 64 * 81;
    float* Vs = Ks + 64 * 81;
    float* Ps = Vs + 64 * 81;       // 64*64

    const int qt   = blockIdx.x;
    const int h    = blockIdx.y;
    const int b    = blockIdx.z;
    const int tid  = threadIdx.x;
    const int lane = tid & 31;
    const int w    = tid >> 5;
    const int r0   = w << 3;
    const float scale = 0.11180339887498949f;   // 1/sqrt(80)

    // Load Q tile (64 rows x 80)
    for (int t = tid; t < 64 * 20; t += 256) {
        const int r = t / 20, c = (t % 20) * 4;
        float4 v = *(const float4*)&qkv[((size_t)(b * S_ + qt * 64 + r)) * QKV_N + h * HD_ + c];
        Qs[r * 81 + c + 0] = v.x; Qs[r * 81 + c + 1] = v.y;
        Qs[r * 81 + c + 2] = v.z; Qs[r * 81 + c + 3] = v.w;
    }

    float o0[8], o1[8], o2[8], mx[8], l[8];
    #pragma unroll
    for (int r = 0; r < 8; ++r) { o0[r] = o1[r] = o2[r] = 0.f; mx[r] = -1e30f; l[r] = 0.f; }
    __syncthreads();

    for (int kt = 0; kt <= qt; ++kt) {
        // Load K, V tiles
        for (int t = tid; t < 64 * 20; t += 256) {
            const int r = t / 20, c = (t % 20) * 4;
            const size_t g = ((size_t)(b * S_ + kt * 64 + r)) * QKV_N + h * HD_ + c;
            float4 kv = *(const float4*)&qkv[g + D_];
            Ks[r * 81 + c + 0] = kv.x; Ks[r * 81 + c + 1] = kv.y;
            Ks[r * 81 + c + 2] = kv.z; Ks[r * 81 + c + 3] = kv.w;
            float4 vv = *(const float4*)&qkv[g + 2 * D_];
            Vs[r * 81 + c + 0] = vv.x; Vs[r * 81 + c + 1] = vv.y;
            Vs[r * 81 + c + 2] = vv.z; Vs[r * 81 + c + 3] = vv.w;
        }
        __syncthreads();

        // Scores: lane owns keys (lane, lane+32) for this warp's 8 rows
        float s0[8], s1[8];
        #pragma unroll
        for (int r = 0; r < 8; ++r) { s0[r] = 0.f; s1[r] = 0.f; }
        const float* kp0 = &Ks[lane * 81];
        const float* kp1 = &Ks[(lane + 32) * 81];
        #pragma unroll 4
        for (int d = 0; d < 80; ++d) {
            const float k0 = kp0[d], k1 = kp1[d];
            #pragma unroll
            for (int r = 0; r < 8; ++r) {
                const float q = Qs[(r0 + r) * 81 + d];
                s0[r] += q * k0;
                s1[r] += q * k1;
            }
        }

        const bool diag = (kt == qt);
        #pragma unroll
        for (int r = 0; r < 8; ++r) {
            float a0 = s0[r] * scale, a1 = s1[r] * scale;
            if (diag) {
                const int row = r0 + r;
                if (lane      > row) a0 = -1e30f;
                if (lane + 32 > row) a1 = -1e30f;
            }
            float mt = fmaxf(a0, a1);
            #pragma unroll
            for (int off = 16; off; off >>= 1)
                mt = fmaxf(mt, __shfl_xor_sync(0xffffffffu, mt, off));
            const float mn = fmaxf(mx[r], mt);
            const float p0 = __expf(a0 - mn);
            const float p1 = __expf(a1 - mn);
            const float corr = __expf(mx[r] - mn);
            mx[r] = mn;
            float ps = p0 + p1;
            #pragma unroll
            for (int off = 16; off; off >>= 1)
                ps += __shfl_xor_sync(0xffffffffu, ps, off);
            l[r] = l[r] * corr + ps;
            o0[r] *= corr; o1[r] *= corr; o2[r] *= corr;
            Ps[(r0 + r) * 64 + lane]      = p0;
            Ps[(r0 + r) * 64 + lane + 32] = p1;
        }
        __syncwarp();

        // PV: lane owns dims (lane, lane+32, 64+(lane&15))
        const float* vp0 = &Vs[lane];
        const float* vp1 = &Vs[lane + 32];
        const float* vp2 = &Vs[64 + (lane & 15)];
        #pragma unroll 2
        for (int j = 0; j < 64; ++j) {
            const float v0 = vp0[j * 81];
            const float v1 = vp1[j * 81];
            const float v2 = vp2[j * 81];
            #pragma unroll
            for (int r = 0; r < 8; ++r) {
                const float p = Ps[(r0 + r) * 64 + j];
                o0[r] += p * v0;
                o1[r] += p * v1;
                o2[r] += p * v2;
            }
        }
        __syncthreads();
    }

    // Epilogue: normalize + write ctx [b, s, h, hd]
    #pragma unroll
    for (int r = 0; r < 8; ++r) {
        const float inv = 1.0f / l[r];
        const size_t base = ((size_t)(b * S_ + qt * 64 + r0 + r)) * D_ + h * HD_;
        ctx[base + lane]      = o0[r] * inv;
        ctx[base + lane + 32] = o1[r] * inv;
        if (lane < 16) ctx[base + lane + 64] = o2[r] * inv;
    }
}

// ---------------------------------------------------------------------------
// Launch
// ---------------------------------------------------------------------------
extern "C" void kernel_launch(void* const* d_in, const int* in_sizes, int n_in,
                              void* d_out, int out_size)
{
    const float* x      = (const float*)d_in[0];
    const float* wqkv_w = (const float*)d_in[1];
    const float* wqkv_b = (const float*)d_in[2];
    const float* out_w  = (const float*)d_in[3];
    const float* out_b  = (const float*)d_in[4];
    float* out = (float*)d_out;

    float *qkv, *ctx;
    cudaGetSymbolAddress((void**)&qkv, g_qkv);
    cudaGetSymbolAddress((void**)&ctx, g_ctx);

    cudaFuncSetAttribute(attn_kernel,
                         cudaFuncAttributeMaxDynamicSharedMemorySize, ATTN_SMEM);

    // 1) QKV = X @ Wqkv^T + b
    dim3 g1(QKV_N / 128, M_ROWS / 128);
    sgemm_nt_bias<128, 128, 16><<<g1, 256>>>(x, wqkv_w, wqkv_b, qkv,
                                             M_ROWS, QKV_N, D_);
    // 2) RoPE on q,k
    const int rope_total = B_ * S_ * 2 * H_ * (RD_ / 2);
    rope_kernel<<<rope_total / 256, 256>>>(qkv);

    // 3) causal attention -> ctx
    dim3 ga(S_ / 64, H_, B_);
    attn_kernel<<<ga, 256, ATTN_SMEM>>>(qkv, ctx);

    // 4) out = ctx @ Wout^T + b
    dim3 g2(D_ / 128, M_ROWS / 128);
    sgemm_nt_bias<128, 128, 16><<<g2, 256>>>(ctx, out_w, out_b, out,
                                             M_ROWS, D_, D_);
}

// round 2
// speedup vs baseline: 1.6801x; 1.6801x over previous
#include <cuda_runtime.h>
#include <cuda_bf16.h>
#include <cstdint>

// Problem constants
#define B_  2
#define S_  2048
#define D_  2560
#define H_  32
#define HD_ 80
#define RD_ 32

constexpr int M_ROWS = B_ * S_;       // 4096
constexpr int QKV_N  = 3 * D_;        // 7680

// Scratch (no allocation allowed -> __device__ globals)
__device__ float g_qkv[(size_t)M_ROWS * QKV_N];   // ~126 MB
__device__ float g_ctx[(size_t)M_ROWS * D_];      // ~42 MB

// ---------------------------------------------------------------------------
// mma.sync helpers (bf16 HMMA, fp32 accum)
// ---------------------------------------------------------------------------
__device__ __forceinline__ void ldsm4(uint32_t& r0, uint32_t& r1,
                                      uint32_t& r2, uint32_t& r3,
                                      const __nv_bfloat16* p)
{
    uint32_t addr = (uint32_t)__cvta_generic_to_shared(p);
    asm volatile("ldmatrix.sync.aligned.m8n8.x4.shared.b16 {%0,%1,%2,%3}, [%4];"
                 : "=r"(r0), "=r"(r1), "=r"(r2), "=r"(r3) : "r"(addr));
}

__device__ __forceinline__ void mma16816(float* c, const uint32_t* a,
                                         uint32_t b0, uint32_t b1)
{
    asm volatile(
        "mma.sync.aligned.m16n8k16.row.col.f32.bf16.bf16.f32 "
        "{%0,%1,%2,%3}, {%4,%5,%6,%7}, {%8,%9}, {%0,%1,%2,%3};"
        : "+f"(c[0]), "+f"(c[1]), "+f"(c[2]), "+f"(c[3])
        : "r"(a[0]), "r"(a[1]), "r"(a[2]), "r"(a[3]), "r"(b0), "r"(b1));
}

// Convert float4 -> bf16 hi (rn) + bf16 lo (residual), store 8B each.
__device__ __forceinline__ void cvt_store(float4 v, __nv_bfloat16* hi,
                                          __nv_bfloat16* lo)
{
    __nv_bfloat162 h0 = __floats2bfloat162_rn(v.x, v.y);
    __nv_bfloat162 h1 = __floats2bfloat162_rn(v.z, v.w);
    float2 f0 = __bfloat1622float2(h0);
    float2 f1 = __bfloat1622float2(h1);
    __nv_bfloat162 l0 = __floats2bfloat162_rn(v.x - f0.x, v.y - f0.y);
    __nv_bfloat162 l1 = __floats2bfloat162_rn(v.z - f1.x, v.w - f1.y);
    uint2 hp = make_uint2(*(uint32_t*)&h0, *(uint32_t*)&h1);
    uint2 lp = make_uint2(*(uint32_t*)&l0, *(uint32_t*)&l1);
    *(uint2*)hi = hp;
    *(uint2*)lo = lp;
}

// ---------------------------------------------------------------------------
// bf16x3 split-precision NT GEMM: C[M,N] = A[M,K] @ W[N,K]^T + bias
// BM=BN=128, BK=32, 256 threads (8 warps, each 32x64). fp32-equivalent
// accuracy via a_hi*b_hi + a_hi*b_lo + a_lo*b_hi.
// ---------------------------------------------------------------------------
#define LDS_ 40   // smem row stride in bf16 (pad 32 -> 40, conflict-free ldsm)

__global__ __launch_bounds__(256)
void gemm_bf16x3(const float* __restrict__ A, const float* __restrict__ W,
                 const float* __restrict__ bias, float* __restrict__ C,
                 int M, int N, int K)
{
    __shared__ __nv_bfloat16 Ahi[128 * LDS_], Alo[128 * LDS_];
    __shared__ __nv_bfloat16 Bhi[128 * LDS_], Blo[128 * LDS_];

    const int tid  = threadIdx.x;
    const int lane = tid & 31;
    const int wid  = tid >> 5;
    const int wm0  = (wid & 3) * 32;
    const int wn0  = (wid >> 2) * 64;
    const int bm   = blockIdx.y * 128;
    const int bn   = blockIdx.x * 128;

    float acc[2][8][4];
    #pragma unroll
    for (int mi = 0; mi < 2; ++mi)
        #pragma unroll
        for (int ni = 0; ni < 8; ++ni)
            #pragma unroll
            for (int j = 0; j < 4; ++j) acc[mi][ni][j] = 0.f;

    float4 ra[4], rb[4];
    const int s_row = tid >> 3;      // 0..31 base pattern
    const int s_c4  = tid & 7;

    // prologue load k0=0
    #pragma unroll
    for (int i = 0; i < 4; ++i) {
        const int row = s_row + i * 32;
        ra[i] = *(const float4*)&A[(size_t)(bm + row) * K + s_c4 * 4];
        rb[i] = *(const float4*)&W[(size_t)(bn + row) * K + s_c4 * 4];
    }
    #pragma unroll
    for (int i = 0; i < 4; ++i) {
        const int row = s_row + i * 32;
        cvt_store(ra[i], &Ahi[row * LDS_ + s_c4 * 4], &Alo[row * LDS_ + s_c4 * 4]);
        cvt_store(rb[i], &Bhi[row * LDS_ + s_c4 * 4], &Blo[row * LDS_ + s_c4 * 4]);
    }
    __syncthreads();

    const int lr = lane & 7;
    const int g  = lane >> 3;

    for (int k0 = 32; ; k0 += 32) {
        const bool more = (k0 < K);
        if (more) {
            #pragma unroll
            for (int i = 0; i < 4; ++i) {
                const int row = s_row + i * 32;
                ra[i] = *(const float4*)&A[(size_t)(bm + row) * K + k0 + s_c4 * 4];
                rb[i] = *(const float4*)&W[(size_t)(bn + row) * K + k0 + s_c4 * 4];
            }
        }

        #pragma unroll
        for (int ks = 0; ks < 2; ++ks) {
            uint32_t ah[2][4], al[2][4];
            #pragma unroll
            for (int mi = 0; mi < 2; ++mi) {
                const int row = wm0 + mi * 16 + lr + (g & 1) * 8;
                const int col = ks * 16 + (g >> 1) * 8;
                ldsm4(ah[mi][0], ah[mi][1], ah[mi][2], ah[mi][3],
                      &Ahi[row * LDS_ + col]);
                ldsm4(al[mi][0], al[mi][1], al[mi][2], al[mi][3],
                      &Alo[row * LDS_ + col]);
            }
            #pragma unroll
            for (int np = 0; np < 4; ++np) {
                const int row = wn0 + np * 16 + lr + (g >> 1) * 8;
                const int col = ks * 16 + (g & 1) * 8;
                uint32_t bh[4], bl[4];
                ldsm4(bh[0], bh[1], bh[2], bh[3], &Bhi[row * LDS_ + col]);
                ldsm4(bl[0], bl[1], bl[2], bl[3], &Blo[row * LDS_ + col]);
                #pragma unroll
                for (int half = 0; half < 2; ++half) {
                    const int ni = np * 2 + half;
                    #pragma unroll
                    for (int mi = 0; mi < 2; ++mi) {
                        mma16816(acc[mi][ni], ah[mi], bh[half * 2], bh[half * 2 + 1]);
                        mma16816(acc[mi][ni], ah[mi], bl[half * 2], bl[half * 2 + 1]);
                        mma16816(acc[mi][ni], al[mi], bh[half * 2], bh[half * 2 + 1]);
                    }
                }
            }
        }

        if (!more) break;
        __syncthreads();
        #pragma unroll
        for (int i = 0; i < 4; ++i) {
            const int row = s_row + i * 32;
            cvt_store(ra[i], &Ahi[row * LDS_ + s_c4 * 4], &Alo[row * LDS_ + s_c4 * 4]);
            cvt_store(rb[i], &Bhi[row * LDS_ + s_c4 * 4], &Blo[row * LDS_ + s_c4 * 4]);
        }
        __syncthreads();
    }

    // Epilogue: bias + store
    #pragma unroll
    for (int ni = 0; ni < 8; ++ni) {
        const int col = bn + wn0 + ni * 8 + (lane & 3) * 2;
        const float2 bv = *(const float2*)&bias[col];
        #pragma unroll
        for (int mi = 0; mi < 2; ++mi) {
            const int row = bm + wm0 + mi * 16 + (lane >> 2);
            float2 v0 = make_float2(acc[mi][ni][0] + bv.x, acc[mi][ni][1] + bv.y);
            float2 v1 = make_float2(acc[mi][ni][2] + bv.x, acc[mi][ni][3] + bv.y);
            *(float2*)&C[(size_t)row * N + col]       = v0;
            *(float2*)&C[(size_t)(row + 8) * N + col] = v1;
        }
    }
}

// ---------------------------------------------------------------------------
// RoPE (in-place on qkv)
// ---------------------------------------------------------------------------
__global__ void rope_kernel(float* __restrict__ qkv)
{
    int idx = blockIdx.x * blockDim.x + threadIdx.x;
    const int total = B_ * S_ * 2 * H_ * (RD_ / 2);
    if (idx >= total) return;
    const int i    = idx & 15;  idx >>= 4;
    const int h    = idx & 31;  idx >>= 5;
    const int part = idx & 1;   idx >>= 1;
    const int s    = idx & (S_ - 1); idx >>= 11;
    const int b    = idx;

    const double inv = exp2(-(double)i * (13.287712379549449 / 16.0));
    const float ang  = (float)((double)s * inv);
    const float c  = cosf(ang);
    const float si = sinf(ang);

    const size_t base = ((size_t)(b * S_ + s)) * QKV_N + (size_t)part * D_ + h * HD_;
    const float t1 = qkv[base + i];
    const float t2 = qkv[base + 16 + i];
    qkv[base + i]      = t1 * c  - t2 * si;
    qkv[base + 16 + i] = t1 * si + t2 * c;
}

// ---------------------------------------------------------------------------
// Causal flash attention, fp32 (unchanged from round 1)
// ---------------------------------------------------------------------------
constexpr int ATTN_SMEM = (3 * 64 * 81 + 64 * 64) * 4;

__global__ __launch_bounds__(256, 2)
void attn_kernel(const float* __restrict__ qkv, float* __restrict__ ctx)
{
    extern __shared__ float sm[];
    float* Qs = sm;
    float* Ks = Qs + 64 * 81;
    float* Vs = Ks + 64 * 81;
    float* Ps = Vs + 64 * 81;

    const int qt   = blockIdx.x;
    const int h    = blockIdx.y;
    const int b    = blockIdx.z;
    const int tid  = threadIdx.x;
    const int lane = tid & 31;
    const int w    = tid >> 5;
    const int r0   = w << 3;
    const float scale = 0.11180339887498949f;

    for (int t = tid; t < 64 * 20; t += 256) {
        const int r = t / 20, c = (t % 20) * 4;
        float4 v = *(const float4*)&qkv[((size_t)(b * S_ + qt * 64 + r)) * QKV_N + h * HD_ + c];
        Qs[r * 81 + c + 0] = v.x; Qs[r * 81 + c + 1] = v.y;
        Qs[r * 81 + c + 2] = v.z; Qs[r * 81 + c + 3] = v.w;
    }

    float o0[8], o1[8], o2[8], mx[8], l[8];
    #pragma unroll
    for (int r = 0; r < 8; ++r) { o0[r] = o1[r] = o2[r] = 0.f; mx[r] = -1e30f; l[r] = 0.f; }
    __syncthreads();

    for (int kt = 0; kt <= qt; ++kt) {
        for (int t = tid; t < 64 * 20; t += 256) {
            const int r = t / 20, c = (t % 20) * 4;
            const size_t gaddr = ((size_t)(b * S_ + kt * 64 + r)) * QKV_N + h * HD_ + c;
            float4 kv = *(const float4*)&qkv[gaddr + D_];
            Ks[r * 81 + c + 0] = kv.x; Ks[r * 81 + c + 1] = kv.y;
            Ks[r * 81 + c + 2] = kv.z; Ks[r * 81 + c + 3] = kv.w;
            float4 vv = *(const float4*)&qkv[gaddr + 2 * D_];
            Vs[r * 81 + c + 0] = vv.x; Vs[r * 81 + c + 1] = vv.y;
            Vs[r * 81 + c + 2] = vv.z; Vs[r * 81 + c + 3] = vv.w;
        }
        __syncthreads();

        float s0[8], s1[8];
        #pragma unroll
        for (int r = 0; r < 8; ++r) { s0[r] = 0.f; s1[r] = 0.f; }
        const float* kp0 = &Ks[lane * 81];
        const float* kp1 = &Ks[(lane + 32) * 81];
        #pragma unroll 4
        for (int d = 0; d < 80; ++d) {
            const float k0 = kp0[d], k1 = kp1[d];
            #pragma unroll
            for (int r = 0; r < 8; ++r) {
                const float q = Qs[(r0 + r) * 81 + d];
                s0[r] += q * k0;
                s1[r] += q * k1;
            }
        }

        const bool diag = (kt == qt);
        #pragma unroll
        for (int r = 0; r < 8; ++r) {
            float a0 = s0[r] * scale, a1 = s1[r] * scale;
            if (diag) {
                const int row = r0 + r;
                if (lane      > row) a0 = -1e30f;
                if (lane + 32 > row) a1 = -1e30f;
            }
            float mt = fmaxf(a0, a1);
            #pragma unroll
            for (int off = 16; off; off >>= 1)
                mt = fmaxf(mt, __shfl_xor_sync(0xffffffffu, mt, off));
            const float mn = fmaxf(mx[r], mt);
            const float p0 = __expf(a0 - mn);
            const float p1 = __expf(a1 - mn);
            const float corr = __expf(mx[r] - mn);
            mx[r] = mn;
            float ps = p0 + p1;
            #pragma unroll
            for (int off = 16; off; off >>= 1)
                ps += __shfl_xor_sync(0xffffffffu, ps, off);
            l[r] = l[r] * corr + ps;
            o0[r] *= corr; o1[r] *= corr; o2[r] *= corr;
            Ps[(r0 + r) * 64 + lane]      = p0;
            Ps[(r0 + r) * 64 + lane + 32] = p1;
        }
        __syncwarp();

        const float* vp0 = &Vs[lane];
        const float* vp1 = &Vs[lane + 32];
        const float* vp2 = &Vs[64 + (lane & 15)];
        #pragma unroll 2
        for (int j = 0; j < 64; ++j) {
            const float v0 = vp0[j * 81];
            const float v1 = vp1[j * 81];
            const float v2 = vp2[j * 81];
            #pragma unroll
            for (int r = 0; r < 8; ++r) {
                const float p = Ps[(r0 + r) * 64 + j];
                o0[r] += p * v0;
                o1[r] += p * v1;
                o2[r] += p * v2;
            }
        }
        __syncthreads();
    }

    #pragma unroll
    for (int r = 0; r < 8; ++r) {
        const float inv = 1.0f / l[r];
        const size_t base = ((size_t)(b * S_ + qt * 64 + r0 + r)) * D_ + h * HD_;
        ctx[base + lane]      = o0[r] * inv;
        ctx[base + lane + 32] = o1[r] * inv;
        if (lane < 16) ctx[base + lane + 64] = o2[r] * inv;
    }
}

// ---------------------------------------------------------------------------
// Launch
// ---------------------------------------------------------------------------
extern "C" void kernel_launch(void* const* d_in, const int* in_sizes, int n_in,
                              void* d_out, int out_size)
{
    const float* x      = (const float*)d_in[0];
    const float* wqkv_w = (const float*)d_in[1];
    const float* wqkv_b = (const float*)d_in[2];
    const float* out_w  = (const float*)d_in[3];
    const float* out_b  = (const float*)d_in[4];
    float* out = (float*)d_out;

    float *qkv, *ctx;
    cudaGetSymbolAddress((void**)&qkv, g_qkv);
    cudaGetSymbolAddress((void**)&ctx, g_ctx);

    cudaFuncSetAttribute(attn_kernel,
                         cudaFuncAttributeMaxDynamicSharedMemorySize, ATTN_SMEM);

    // 1) QKV = X @ Wqkv^T + b   (bf16x3 tensor-core GEMM)
    dim3 g1(QKV_N / 128, M_ROWS / 128);
    gemm_bf16x3<<<g1, 256>>>(x, wqkv_w, wqkv_b, qkv, M_ROWS, QKV_N, D_);

    // 2) RoPE on q,k
    const int rope_total = B_ * S_ * 2 * H_ * (RD_ / 2);
    rope_kernel<<<rope_total / 256, 256>>>(qkv);

    // 3) causal attention -> ctx
    dim3 ga(S_ / 64, H_, B_);
    attn_kernel<<<ga, 256, ATTN_SMEM>>>(qkv, ctx);

    // 4) out = ctx @ Wout^T + b
    dim3 g2(D_ / 128, M_ROWS / 128);
    gemm_bf16x3<<<g2, 256>>>(ctx, out_w, out_b, out, M_ROWS, D_, D_);
}

// round 4
// speedup vs baseline: 2.7763x; 1.6524x over previous
#include <cuda_runtime.h>
#include <cuda_bf16.h>
#include <cstdint>

// Problem constants
#define B_  2
#define S_  2048
#define D_  2560
#define H_  32
#define HD_ 80
#define RD_ 32

constexpr int M_ROWS = B_ * S_;       // 4096
constexpr int QKV_N  = 3 * D_;        // 7680

// Scratch (no allocation allowed -> __device__ globals)
__device__ float g_qkv[(size_t)M_ROWS * QKV_N];   // ~126 MB
__device__ float g_ctx[(size_t)M_ROWS * D_];      // ~42 MB
// bf16 hi/lo split operands
__device__ __align__(256) __nv_bfloat16 g_ahi[(size_t)M_ROWS * D_];   // x or ctx
__device__ __align__(256) __nv_bfloat16 g_alo[(size_t)M_ROWS * D_];
__device__ __align__(256) __nv_bfloat16 g_whi[(size_t)QKV_N  * D_];   // wqkv
__device__ __align__(256) __nv_bfloat16 g_wlo[(size_t)QKV_N  * D_];
__device__ __align__(256) __nv_bfloat16 g_ohi[(size_t)D_ * D_];       // out_w
__device__ __align__(256) __nv_bfloat16 g_olo[(size_t)D_ * D_];

// ---------------------------------------------------------------------------
// PTX helpers (HMMA / ldmatrix / cp.async)
// ---------------------------------------------------------------------------
__device__ __forceinline__ uint32_t smem_u32(const void* p) {
    uint32_t a;
    asm("{ .reg .u64 t; cvta.to.shared.u64 t, %1; cvt.u32.u64 %0, t; }"
        : "=r"(a) : "l"(p));
    return a;
}
__device__ __forceinline__ void ldsm4u(uint32_t* r, uint32_t addr) {
    asm volatile("ldmatrix.sync.aligned.m8n8.x4.shared.b16 {%0,%1,%2,%3}, [%4];"
                 : "=r"(r[0]), "=r"(r[1]), "=r"(r[2]), "=r"(r[3]) : "r"(addr));
}
__device__ __forceinline__ void ldsm2u(uint32_t& r0, uint32_t& r1, uint32_t addr) {
    asm volatile("ldmatrix.sync.aligned.m8n8.x2.shared.b16 {%0,%1}, [%2];"
                 : "=r"(r0), "=r"(r1) : "r"(addr));
}
__device__ __forceinline__ void ldsm2t(uint32_t& r0, uint32_t& r1, uint32_t addr) {
    asm volatile("ldmatrix.sync.aligned.m8n8.x2.trans.shared.b16 {%0,%1}, [%2];"
                 : "=r"(r0), "=r"(r1) : "r"(addr));
}
__device__ __forceinline__ void mma16816(float* c, const uint32_t* a,
                                         uint32_t b0, uint32_t b1)
{
    asm volatile(
        "mma.sync.aligned.m16n8k16.row.col.f32.bf16.bf16.f32 "
        "{%0,%1,%2,%3}, {%4,%5,%6,%7}, {%8,%9}, {%0,%1,%2,%3};"
        : "+f"(c[0]), "+f"(c[1]), "+f"(c[2]), "+f"(c[3])
        : "r"(a[0]), "r"(a[1]), "r"(a[2]), "r"(a[3]), "r"(b0), "r"(b1));
}
__device__ __forceinline__ void cp_async16(uint32_t dst, const void* src) {
    asm volatile("cp.async.cg.shared.global [%0], [%1], 16;"
                 :: "r"(dst), "l"((unsigned long long)__cvta_generic_to_global(src)));
}
#define CP_COMMIT() asm volatile("cp.async.commit_group;" ::: "memory")

// SW64 swizzle for 64-byte smem rows
#define SWZ64(o) ((o) ^ (((o) >> 3) & 0x30))

// float pair/quad -> bf16 hi + lo residual
__device__ __forceinline__ void split2(float x, float y, uint32_t& hi, uint32_t& lo) {
    __nv_bfloat162 h = __floats2bfloat162_rn(x, y);
    float2 f = __bfloat1622float2(h);
    __nv_bfloat162 l = __floats2bfloat162_rn(x - f.x, y - f.y);
    hi = *(uint32_t*)&h;
    lo = *(uint32_t*)&l;
}
__device__ __forceinline__ void split4(float4 v, uint2& hi, uint2& lo) {
    split2(v.x, v.y, hi.x, lo.x);
    split2(v.z, v.w, hi.y, lo.y);
}

// ---------------------------------------------------------------------------
// fp32 -> bf16 hi/lo split (one-shot, elementwise)
// ---------------------------------------------------------------------------
__global__ void cvt_split(const float4* __restrict__ in, uint2* __restrict__ hi,
                          uint2* __restrict__ lo, int n4)
{
    int i = blockIdx.x * blockDim.x + threadIdx.x;
    if (i >= n4) return;
    uint2 h, l;
    split4(in[i], h, l);
    hi[i] = h;
    lo[i] = l;
}

// ---------------------------------------------------------------------------
// HMMA bf16x3 NT GEMM: C[M,N] = A[M,K] @ W[N,K]^T + bias
// Pre-split bf16 inputs, cp.async double-buffered, BK=32, SW64 smem.
// 256 threads, 8 warps each 32x64. smem = 2 stages x 4 tiles x 8KB = 64KB.
// ---------------------------------------------------------------------------
constexpr int GEMM_SMEM = 65536;

__global__ __launch_bounds__(256, 2)
void gemm_hmma(const __nv_bfloat16* __restrict__ Ahi, const __nv_bfloat16* __restrict__ Alo,
               const __nv_bfloat16* __restrict__ Bhi, const __nv_bfloat16* __restrict__ Blo,
               const float* __restrict__ bias, float* __restrict__ C,
               int M, int N, int K)
{
    extern __shared__ __align__(1024) char gsm[];
    const uint32_t sb = smem_u32(gsm);
    const int tid  = threadIdx.x;
    const int lane = tid & 31;
    const int wid  = tid >> 5;
    const int wm0  = (wid & 3) * 32;
    const int wn0  = (wid >> 2) * 64;
    const int bm   = blockIdx.y * 128;
    const int bn   = blockIdx.x * 128;
    const int lr   = lane & 7;
    const int g    = lane >> 3;

    const __nv_bfloat16* s0 = Ahi + (size_t)bm * K;
    const __nv_bfloat16* s1 = Alo + (size_t)bm * K;
    const __nv_bfloat16* s2 = Bhi + (size_t)bn * K;
    const __nv_bfloat16* s3 = Blo + (size_t)bn * K;

    float acc[2][8][4] = {};

    auto load_stage = [&](int s) {
        const uint32_t st = sb + (uint32_t)(s & 1) * 32768;
        #pragma unroll
        for (int it = 0; it < 8; ++it) {
            const int tile = it >> 1;                   // compile-time
            const int idx  = tid + (it & 1) * 256;      // 0..511
            const int row  = idx >> 2;
            const int c    = idx & 3;
            const __nv_bfloat16* base =
                (tile == 0) ? s0 : (tile == 1) ? s1 : (tile == 2) ? s2 : s3;
            const __nv_bfloat16* gp = base + (size_t)row * K + s * 32 + c * 8;
            cp_async16(st + tile * 8192 + SWZ64((uint32_t)(row * 64 + c * 16)), gp);
        }
        CP_COMMIT();
    };

    const int nst = K >> 5;
    load_stage(0);

    for (int s = 0; s < nst; ++s) {
        if (s + 1 < nst) {
            load_stage(s + 1);
            asm volatile("cp.async.wait_group 1;" ::: "memory");
        } else {
            asm volatile("cp.async.wait_group 0;" ::: "memory");
        }
        __syncthreads();

        const uint32_t st = sb + (uint32_t)(s & 1) * 32768;
        #pragma unroll
        for (int ks = 0; ks < 2; ++ks) {
            uint32_t ah[2][4], al[2][4];
            #pragma unroll
            for (int mi = 0; mi < 2; ++mi) {
                const uint32_t ro = (uint32_t)((wm0 + mi * 16 + lr + (g & 1) * 8) * 64
                                               + ks * 32 + (g >> 1) * 16);
                ldsm4u(ah[mi], st + SWZ64(ro));
                ldsm4u(al[mi], st + 8192 + SWZ64(ro));
            }
            #pragma unroll
            for (int np = 0; np < 4; ++np) {
                const uint32_t ro = (uint32_t)((wn0 + np * 16 + lr + (g >> 1) * 8) * 64
                                               + ks * 32 + (g & 1) * 16);
                uint32_t bh[4], bl[4];
                ldsm4u(bh, st + 16384 + SWZ64(ro));
                ldsm4u(bl, st + 24576 + SWZ64(ro));
                #pragma unroll
                for (int half = 0; half < 2; ++half) {
                    const int ni = np * 2 + half;
                    #pragma unroll
                    for (int mi = 0; mi < 2; ++mi) {
                        mma16816(acc[mi][ni], ah[mi], bh[half * 2], bh[half * 2 + 1]);
                        mma16816(acc[mi][ni], ah[mi], bl[half * 2], bl[half * 2 + 1]);
                        mma16816(acc[mi][ni], al[mi], bh[half * 2], bh[half * 2 + 1]);
                    }
                }
            }
        }
        __syncthreads();
    }

    // Epilogue: bias + store
    #pragma unroll
    for (int ni = 0; ni < 8; ++ni) {
        const int col = bn + wn0 + ni * 8 + (lane & 3) * 2;
        const float2 bv = *(const float2*)&bias[col];
        #pragma unroll
        for (int mi = 0; mi < 2; ++mi) {
            const int row = bm + wm0 + mi * 16 + (lane >> 2);
            *(float2*)&C[(size_t)row * N + col] =
                make_float2(acc[mi][ni][0] + bv.x, acc[mi][ni][1] + bv.y);
            *(float2*)&C[(size_t)(row + 8) * N + col] =
                make_float2(acc[mi][ni][2] + bv.x, acc[mi][ni][3] + bv.y);
        }
    }
}

// ---------------------------------------------------------------------------
// RoPE (in-place on qkv)
// ---------------------------------------------------------------------------
__global__ void rope_kernel(float* __restrict__ qkv)
{
    int idx = blockIdx.x * blockDim.x + threadIdx.x;
    const int total = B_ * S_ * 2 * H_ * (RD_ / 2);
    if (idx >= total) return;
    const int i    = idx & 15;  idx >>= 4;
    const int h    = idx & 31;  idx >>= 5;
    const int part = idx & 1;   idx >>= 1;
    const int s    = idx & (S_ - 1); idx >>= 11;
    const int b    = idx;

    const double inv = exp2(-(double)i * (13.287712379549449 / 16.0));
    const float ang  = (float)((double)s * inv);
    const float c  = cosf(ang);
    const float si = sinf(ang);

    const size_t base = ((size_t)(b * S_ + s)) * QKV_N + (size_t)part * D_ + h * HD_;
    const float t1 = qkv[base + i];
    const float t2 = qkv[base + 16 + i];
    qkv[base + i]      = t1 * c  - t2 * si;
    qkv[base + 16 + i] = t1 * si + t2 * c;
}

// ---------------------------------------------------------------------------
// Causal flash attention, HMMA bf16x3 (QK and PV on tensor cores).
// CTA: 64 q rows x one (b,h); 4 warps, each 16 q rows. 64-key tiles.
// smem (bf16): Qhi/Qlo/Khi/Klo/Vhi/Vlo each [64][88] (176B rows, conflict-free
// ldmatrix). V consumed via ldmatrix.trans (no transposed stores needed).
// ---------------------------------------------------------------------------
constexpr int ATQ  = 0;
constexpr int ATQL = 5632;
constexpr int ATKH = 11264;
constexpr int ATKL = 16896;
constexpr int ATVH = 22528;
constexpr int ATVL = 28160;
constexpr int ATTN_SMEM = 33792 * 2;   // 67584 bytes

__global__ __launch_bounds__(128)
void attn_tc(const float* __restrict__ qkv, float* __restrict__ ctx)
{
    extern __shared__ __align__(1024) __nv_bfloat16 smb[];
    const uint32_t sb = smem_u32(smb);
    const int qt   = gridDim.x - 1 - blockIdx.x;   // big tiles first (tail balance)
    const int h    = blockIdx.y;
    const int b    = blockIdx.z;
    const int tid  = threadIdx.x;
    const int lane = tid & 31;
    const int wid  = tid >> 5;
    const int wm   = wid * 16;
    const int lr   = lane & 7;
    const int g    = lane >> 3;
    const float scale = 0.11180339887498949f;   // 1/sqrt(80)

    // Load + split Q tile: rows = q, 80 dims, 88-elem padded rows
    for (int t = tid; t < 64 * 20; t += 128) {
        const int r = t / 20, c4 = (t % 20) * 4;
        float4 v = *(const float4*)&qkv[((size_t)(b * S_ + qt * 64 + r)) * QKV_N + h * HD_ + c4];
        uint2 hi, lo;
        split4(v, hi, lo);
        *(uint2*)(smb + ATQ  + r * 88 + c4) = hi;
        *(uint2*)(smb + ATQL + r * 88 + c4) = lo;
    }
    __syncthreads();

    // Q fragments (invariant over kt): 5 k16 steps covering d=80
    uint32_t qh[5][4], ql[5][4];
    #pragma unroll
    for (int ks = 0; ks < 5; ++ks) {
        const uint32_t ro = (uint32_t)((wm + lr + (g & 1) * 8) * 176 + ks * 32 + (g >> 1) * 16);
        ldsm4u(qh[ks], sb + ATQ * 2 + ro);
        ldsm4u(ql[ks], sb + ATQL * 2 + ro);
    }

    float o[10][4] = {};
    float mx0 = -1e30f, mx1 = -1e30f, l0 = 0.f, l1 = 0.f;

    for (int kt = 0; kt <= qt; ++kt) {
        __syncthreads();   // prior tile's ldmatrix reads done before overwrite
        for (int t = tid; t < 64 * 20; t += 128) {
            const int r = t / 20, c4 = (t % 20) * 4;
            const size_t ga = ((size_t)(b * S_ + kt * 64 + r)) * QKV_N + h * HD_ + c4;
            uint2 hi, lo;
            float4 kv = *(const float4*)&qkv[ga + D_];
            split4(kv, hi, lo);
            *(uint2*)(smb + ATKH + r * 88 + c4) = hi;
            *(uint2*)(smb + ATKL + r * 88 + c4) = lo;
            float4 vv = *(const float4*)&qkv[ga + 2 * D_];
            split4(vv, hi, lo);
            *(uint2*)(smb + ATVH + r * 88 + c4) = hi;
            *(uint2*)(smb + ATVL + r * 88 + c4) = lo;
        }
        __syncthreads();

        // ---- scores: S = Q K^T (bf16x3), 8 n8 blocks of keys ----
        float s[8][4];
        #pragma unroll
        for (int nb = 0; nb < 8; ++nb) {
            s[nb][0] = s[nb][1] = s[nb][2] = s[nb][3] = 0.f;
            #pragma unroll
            for (int ks = 0; ks < 5; ++ks) {
                const uint32_t ro = (uint32_t)((nb * 8 + lr) * 176 + ks * 32 + (g & 1) * 16);
                uint32_t kh0, kh1, kl0, kl1;
                ldsm2u(kh0, kh1, sb + ATKH * 2 + ro);
                ldsm2u(kl0, kl1, sb + ATKL * 2 + ro);
                mma16816(s[nb], qh[ks], kh0, kh1);
                mma16816(s[nb], qh[ks], kl0, kl1);
                mma16816(s[nb], ql[ks], kh0, kh1);
            }
            #pragma unroll
            for (int j = 0; j < 4; ++j) s[nb][j] *= scale;
            if (kt == qt) {   // causal mask on the diagonal tile
                const int r0 = wm + (lane >> 2);
                const int c0 = nb * 8 + (lane & 3) * 2;
                if (c0     > r0)     s[nb][0] = -1e30f;
                if (c0 + 1 > r0)     s[nb][1] = -1e30f;
                if (c0     > r0 + 8) s[nb][2] = -1e30f;
                if (c0 + 1 > r0 + 8) s[nb][3] = -1e30f;
            }
        }

        // ---- online softmax (rows r0 = wm+(lane>>2), r1 = r0+8) ----
        float m0 = -1e30f, m1 = -1e30f;
        #pragma unroll
        for (int nb = 0; nb < 8; ++nb) {
            m0 = fmaxf(m0, fmaxf(s[nb][0], s[nb][1]));
            m1 = fmaxf(m1, fmaxf(s[nb][2], s[nb][3]));
        }
        m0 = fmaxf(m0, __shfl_xor_sync(0xffffffffu, m0, 1));
        m0 = fmaxf(m0, __shfl_xor_sync(0xffffffffu, m0, 2));
        m1 = fmaxf(m1, __shfl_xor_sync(0xffffffffu, m1, 1));
        m1 = fmaxf(m1, __shfl_xor_sync(0xffffffffu, m1, 2));
        const float mn0 = fmaxf(mx0, m0), mn1 = fmaxf(mx1, m1);
        const float corr0 = __expf(mx0 - mn0), corr1 = __expf(mx1 - mn1);
        mx0 = mn0; mx1 = mn1;
        float sum0 = 0.f, sum1 = 0.f;
        #pragma unroll
        for (int nb = 0; nb < 8; ++nb) {
            s[nb][0] = __expf(s[nb][0] - mn0);
            s[nb][1] = __expf(s[nb][1] - mn0);
            s[nb][2] = __expf(s[nb][2] - mn1);
            s[nb][3] = __expf(s[nb][3] - mn1);
            sum0 += s[nb][0] + s[nb][1];
            sum1 += s[nb][2] + s[nb][3];
        }
        sum0 += __shfl_xor_sync(0xffffffffu, sum0, 1);
        sum0 += __shfl_xor_sync(0xffffffffu, sum0, 2);
        sum1 += __shfl_xor_sync(0xffffffffu, sum1, 1);
        sum1 += __shfl_xor_sync(0xffffffffu, sum1, 2);
        l0 = l0 * corr0 + sum0;
        l1 = l1 * corr1 + sum1;
        #pragma unroll
        for (int nd = 0; nd < 10; ++nd) {
            o[nd][0] *= corr0; o[nd][1] *= corr0;
            o[nd][2] *= corr1; o[nd][3] *= corr1;
        }

        // ---- P -> bf16 hi/lo A-fragments (4 k16 blocks of keys) ----
        uint32_t ph[4][4], pl[4][4];
        #pragma unroll
        for (int kb = 0; kb < 4; ++kb) {
            split2(s[2 * kb][0],     s[2 * kb][1],     ph[kb][0], pl[kb][0]);
            split2(s[2 * kb][2],     s[2 * kb][3],     ph[kb][1], pl[kb][1]);
            split2(s[2 * kb + 1][0], s[2 * kb + 1][1], ph[kb][2], pl[kb][2]);
            split2(s[2 * kb + 1][2], s[2 * kb + 1][3], ph[kb][3], pl[kb][3]);
        }

        // ---- O += P V (bf16x3), V via ldmatrix.trans ----
        #pragma unroll
        for (int nd = 0; nd < 10; ++nd) {
            #pragma unroll
            for (int kb = 0; kb < 4; ++kb) {
                const uint32_t ro = (uint32_t)((kb * 16 + (g & 1) * 8 + lr) * 176 + nd * 16);
                uint32_t vh0, vh1, vl0, vl1;
                ldsm2t(vh0, vh1, sb + ATVH * 2 + ro);
                ldsm2t(vl0, vl1, sb + ATVL * 2 + ro);
                mma16816(o[nd], ph[kb], vh0, vh1);
                mma16816(o[nd], ph[kb], vl0, vl1);
                mma16816(o[nd], pl[kb], vh0, vh1);
            }
        }
    }

    // Epilogue: normalize + write ctx [b, s, h*80 + d]
    const float inv0 = 1.f / l0, inv1 = 1.f / l1;
    const int r0 = qt * 64 + wm + (lane >> 2);
    #pragma unroll
    for (int nd = 0; nd < 10; ++nd) {
        const int col = h * HD_ + nd * 8 + (lane & 3) * 2;
        *(float2*)&ctx[((size_t)(b * S_ + r0)) * D_ + col] =
            make_float2(o[nd][0] * inv0, o[nd][1] * inv0);
        *(float2*)&ctx[((size_t)(b * S_ + r0 + 8)) * D_ + col] =
            make_float2(o[nd][2] * inv1, o[nd][3] * inv1);
    }
}

// ---------------------------------------------------------------------------
// Launch
// ---------------------------------------------------------------------------
extern "C" void kernel_launch(void* const* d_in, const int* in_sizes, int n_in,
                              void* d_out, int out_size)
{
    const float* x      = (const float*)d_in[0];
    const float* wqkv_w = (const float*)d_in[1];
    const float* wqkv_b = (const float*)d_in[2];
    const float* out_w  = (const float*)d_in[3];
    const float* out_b  = (const float*)d_in[4];
    float* out = (float*)d_out;

    float *qkv, *ctx;
    __nv_bfloat16 *ahi, *alo, *whi, *wlo, *ohi, *olo;
    cudaGetSymbolAddress((void**)&qkv, g_qkv);
    cudaGetSymbolAddress((void**)&ctx, g_ctx);
    cudaGetSymbolAddress((void**)&ahi, g_ahi);
    cudaGetSymbolAddress((void**)&alo, g_alo);
    cudaGetSymbolAddress((void**)&whi, g_whi);
    cudaGetSymbolAddress((void**)&wlo, g_wlo);
    cudaGetSymbolAddress((void**)&ohi, g_ohi);
    cudaGetSymbolAddress((void**)&olo, g_olo);

    cudaFuncSetAttribute(gemm_hmma,
                         cudaFuncAttributeMaxDynamicSharedMemorySize, GEMM_SMEM);
    cudaFuncSetAttribute(attn_tc,
                         cudaFuncAttributeMaxDynamicSharedMemorySize, ATTN_SMEM);

    // 0) split operands into bf16 hi/lo
    {
        const int n4x = M_ROWS * D_ / 4;
        cvt_split<<<n4x / 256, 256>>>((const float4*)x, (uint2*)ahi, (uint2*)alo, n4x);
        const int n4w = QKV_N * D_ / 4;
        cvt_split<<<n4w / 256, 256>>>((const float4*)wqkv_w, (uint2*)whi, (uint2*)wlo, n4w);
        const int n4o = D_ * D_ / 4;
        cvt_split<<<n4o / 256, 256>>>((const float4*)out_w, (uint2*)ohi, (uint2*)olo, n4o);
    }

    // 1) QKV = X @ Wqkv^T + b   (HMMA bf16x3)
    dim3 g1(QKV_N / 128, M_ROWS / 128);
    gemm_hmma<<<g1, 256, GEMM_SMEM>>>(ahi, alo, whi, wlo, wqkv_b, qkv,
                                      M_ROWS, QKV_N, D_);

    // 2) RoPE on q,k
    const int rope_total = B_ * S_ * 2 * H_ * (RD_ / 2);
    rope_kernel<<<rope_total / 256, 256>>>(qkv);

    // 3) causal attention -> ctx   (HMMA bf16x3)
    dim3 ga(S_ / 64, H_, B_);
    attn_tc<<<ga, 128, ATTN_SMEM>>>(qkv, ctx);

    // 4) split ctx, then out = ctx @ Wout^T + b
    {
        const int n4c = M_ROWS * D_ / 4;
        cvt_split<<<n4c / 256, 256>>>((const float4*)ctx, (uint2*)ahi, (uint2*)alo, n4c);
    }
    dim3 g2(D_ / 128, M_ROWS / 128);
    gemm_hmma<<<g2, 256, GEMM_SMEM>>>(ahi, alo, ohi, olo, out_b, out,
                                      M_ROWS, D_, D_);
}

// round 5
// speedup vs baseline: 2.8709x; 1.0341x over previous
#include <cuda_runtime.h>
#include <cuda_bf16.h>
#include <cstdint>

// Problem constants
#define B_  2
#define S_  2048
#define D_  2560
#define H_  32
#define HD_ 80
#define RD_ 32

constexpr int M_ROWS = B_ * S_;       // 4096
constexpr int QKV_N  = 3 * D_;        // 7680

// Scratch (no allocation allowed -> __device__ globals)
__device__ float g_qkv[(size_t)M_ROWS * QKV_N];   // fp32 qkv (pre-split)
// bf16 hi/lo split operands for GEMMs
__device__ __align__(256) __nv_bfloat16 g_ahi[(size_t)M_ROWS * D_];   // x / ctx
__device__ __align__(256) __nv_bfloat16 g_alo[(size_t)M_ROWS * D_];
__device__ __align__(256) __nv_bfloat16 g_whi[(size_t)QKV_N  * D_];
__device__ __align__(256) __nv_bfloat16 g_wlo[(size_t)QKV_N  * D_];
__device__ __align__(256) __nv_bfloat16 g_ohi[(size_t)D_ * D_];
__device__ __align__(256) __nv_bfloat16 g_olo[(size_t)D_ * D_];
// head-major pre-split q/k/v: [b][h][s][80]
constexpr size_t HM_SZ = (size_t)B_ * H_ * S_ * HD_;
__device__ __align__(256) __nv_bfloat16 g_qh[HM_SZ], g_ql[HM_SZ];
__device__ __align__(256) __nv_bfloat16 g_kh[HM_SZ], g_kl[HM_SZ];
__device__ __align__(256) __nv_bfloat16 g_vh[HM_SZ], g_vl[HM_SZ];

// ---------------------------------------------------------------------------
// PTX helpers
// ---------------------------------------------------------------------------
__device__ __forceinline__ uint32_t smem_u32(const void* p) {
    uint32_t a;
    asm("{ .reg .u64 t; cvta.to.shared.u64 t, %1; cvt.u32.u64 %0, t; }"
        : "=r"(a) : "l"(p));
    return a;
}
__device__ __forceinline__ void ldsm4u(uint32_t* r, uint32_t addr) {
    asm volatile("ldmatrix.sync.aligned.m8n8.x4.shared.b16 {%0,%1,%2,%3}, [%4];"
                 : "=r"(r[0]), "=r"(r[1]), "=r"(r[2]), "=r"(r[3]) : "r"(addr));
}
__device__ __forceinline__ void ldsm2u(uint32_t& r0, uint32_t& r1, uint32_t addr) {
    asm volatile("ldmatrix.sync.aligned.m8n8.x2.shared.b16 {%0,%1}, [%2];"
                 : "=r"(r0), "=r"(r1) : "r"(addr));
}
__device__ __forceinline__ void ldsm2t(uint32_t& r0, uint32_t& r1, uint32_t addr) {
    asm volatile("ldmatrix.sync.aligned.m8n8.x2.trans.shared.b16 {%0,%1}, [%2];"
                 : "=r"(r0), "=r"(r1) : "r"(addr));
}
__device__ __forceinline__ void mma16816(float* c, const uint32_t* a,
                                         uint32_t b0, uint32_t b1)
{
    asm volatile(
        "mma.sync.aligned.m16n8k16.row.col.f32.bf16.bf16.f32 "
        "{%0,%1,%2,%3}, {%4,%5,%6,%7}, {%8,%9}, {%0,%1,%2,%3};"
        : "+f"(c[0]), "+f"(c[1]), "+f"(c[2]), "+f"(c[3])
        : "r"(a[0]), "r"(a[1]), "r"(a[2]), "r"(a[3]), "r"(b0), "r"(b1));
}
__device__ __forceinline__ void cp_async16(uint32_t dst, const void* src) {
    asm volatile("cp.async.cg.shared.global [%0], [%1], 16;"
                 :: "r"(dst), "l"((unsigned long long)__cvta_generic_to_global(src)));
}
#define CP_COMMIT() asm volatile("cp.async.commit_group;" ::: "memory")

#define SWZ64(o) ((o) ^ (((o) >> 3) & 0x30))

__device__ __forceinline__ void split2(float x, float y, uint32_t& hi, uint32_t& lo) {
    __nv_bfloat162 h = __floats2bfloat162_rn(x, y);
    float2 f = __bfloat1622float2(h);
    __nv_bfloat162 l = __floats2bfloat162_rn(x - f.x, y - f.y);
    hi = *(uint32_t*)&h;
    lo = *(uint32_t*)&l;
}
__device__ __forceinline__ void split4(float4 v, uint2& hi, uint2& lo) {
    split2(v.x, v.y, hi.x, lo.x);
    split2(v.z, v.w, hi.y, lo.y);
}

// ---------------------------------------------------------------------------
// fp32 -> bf16 hi/lo split (elementwise, same layout)
// ---------------------------------------------------------------------------
__global__ void cvt_split(const float4* __restrict__ in, uint2* __restrict__ hi,
                          uint2* __restrict__ lo, int n4)
{
    int i = blockIdx.x * blockDim.x + threadIdx.x;
    if (i >= n4) return;
    uint2 h, l;
    split4(in[i], h, l);
    hi[i] = h;
    lo[i] = l;
}

// ---------------------------------------------------------------------------
// qkv fp32 (post-rope) -> head-major bf16 hi/lo q/k/v arrays
// ---------------------------------------------------------------------------
__global__ void cvt_qkv(const float4* __restrict__ qkv4)
{
    int idx = blockIdx.x * blockDim.x + threadIdx.x;
    const int n4 = M_ROWS * QKV_N / 4;
    if (idx >= n4) return;
    const int col4 = idx % (QKV_N / 4);
    const int rowm = idx / (QKV_N / 4);      // b*S + s
    const int col  = col4 * 4;
    const int part = col / D_;
    const int win  = col % D_;
    const int h    = win / HD_;
    const int d    = win % HD_;
    const int b    = rowm >> 11;
    const int s    = rowm & (S_ - 1);

    uint2 hi, lo;
    split4(qkv4[idx], hi, lo);
    const size_t dst = (((size_t)(b * H_ + h)) * S_ + s) * HD_ + d;
    __nv_bfloat16 *ph, *pl;
    if (part == 0)      { ph = g_qh; pl = g_ql; }
    else if (part == 1) { ph = g_kh; pl = g_kl; }
    else                { ph = g_vh; pl = g_vl; }
    *(uint2*)&ph[dst] = hi;
    *(uint2*)&pl[dst] = lo;
}

// ---------------------------------------------------------------------------
// HMMA bf16x3 NT GEMM, 3-stage cp.async pipeline.
// 256 threads, 8 warps each 32x64. smem = 3 stages x 32KB = 96KB.
// ---------------------------------------------------------------------------
constexpr int GEMM_SMEM = 3 * 32768;

__global__ __launch_bounds__(256, 2)
void gemm_hmma(const __nv_bfloat16* __restrict__ Ahi, const __nv_bfloat16* __restrict__ Alo,
               const __nv_bfloat16* __restrict__ Bhi, const __nv_bfloat16* __restrict__ Blo,
               const float* __restrict__ bias, float* __restrict__ C,
               int M, int N, int K)
{
    extern __shared__ __align__(1024) char gsm[];
    const uint32_t sb = smem_u32(gsm);
    const int tid  = threadIdx.x;
    const int lane = tid & 31;
    const int wid  = tid >> 5;
    const int wm0  = (wid & 3) * 32;
    const int wn0  = (wid >> 2) * 64;
    const int bm   = blockIdx.y * 128;
    const int bn   = blockIdx.x * 128;
    const int lr   = lane & 7;
    const int g    = lane >> 3;

    const __nv_bfloat16* s0 = Ahi + (size_t)bm * K;
    const __nv_bfloat16* s1 = Alo + (size_t)bm * K;
    const __nv_bfloat16* s2 = Bhi + (size_t)bn * K;
    const __nv_bfloat16* s3 = Blo + (size_t)bn * K;

    float acc[2][8][4] = {};

    auto load_stage = [&](int s) {
        const uint32_t st = sb + (uint32_t)(s % 3) * 32768;
        #pragma unroll
        for (int it = 0; it < 8; ++it) {
            const int tile = it >> 1;
            const int idx  = tid + (it & 1) * 256;
            const int row  = idx >> 2;
            const int c    = idx & 3;
            const __nv_bfloat16* base =
                (tile == 0) ? s0 : (tile == 1) ? s1 : (tile == 2) ? s2 : s3;
            const __nv_bfloat16* gp = base + (size_t)row * K + s * 32 + c * 8;
            cp_async16(st + tile * 8192 + SWZ64((uint32_t)(row * 64 + c * 16)), gp);
        }
        CP_COMMIT();
    };

    const int nst = K >> 5;
    load_stage(0);
    load_stage(1);

    for (int s = 0; s < nst; ++s) {
        if (s + 2 < nst) {
            load_stage(s + 2);
            asm volatile("cp.async.wait_group 2;" ::: "memory");
        } else if (s + 1 < nst) {
            asm volatile("cp.async.wait_group 1;" ::: "memory");
        } else {
            asm volatile("cp.async.wait_group 0;" ::: "memory");
        }
        __syncthreads();

        const uint32_t st = sb + (uint32_t)(s % 3) * 32768;
        #pragma unroll
        for (int ks = 0; ks < 2; ++ks) {
            uint32_t ah[2][4], al[2][4];
            #pragma unroll
            for (int mi = 0; mi < 2; ++mi) {
                const uint32_t ro = (uint32_t)((wm0 + mi * 16 + lr + (g & 1) * 8) * 64
                                               + ks * 32 + (g >> 1) * 16);
                ldsm4u(ah[mi], st + SWZ64(ro));
                ldsm4u(al[mi], st + 8192 + SWZ64(ro));
            }
            #pragma unroll
            for (int np = 0; np < 4; ++np) {
                const uint32_t ro = (uint32_t)((wn0 + np * 16 + lr + (g >> 1) * 8) * 64
                                               + ks * 32 + (g & 1) * 16);
                uint32_t bh[4], bl[4];
                ldsm4u(bh, st + 16384 + SWZ64(ro));
                ldsm4u(bl, st + 24576 + SWZ64(ro));
                #pragma unroll
                for (int half = 0; half < 2; ++half) {
                    const int ni = np * 2 + half;
                    #pragma unroll
                    for (int mi = 0; mi < 2; ++mi) {
                        mma16816(acc[mi][ni], ah[mi], bh[half * 2], bh[half * 2 + 1]);
                        mma16816(acc[mi][ni], ah[mi], bl[half * 2], bl[half * 2 + 1]);
                        mma16816(acc[mi][ni], al[mi], bh[half * 2], bh[half * 2 + 1]);
                    }
                }
            }
        }
        __syncthreads();
    }

    #pragma unroll
    for (int ni = 0; ni < 8; ++ni) {
        const int col = bn + wn0 + ni * 8 + (lane & 3) * 2;
        const float2 bv = *(const float2*)&bias[col];
        #pragma unroll
        for (int mi = 0; mi < 2; ++mi) {
            const int row = bm + wm0 + mi * 16 + (lane >> 2);
            *(float2*)&C[(size_t)row * N + col] =
                make_float2(acc[mi][ni][0] + bv.x, acc[mi][ni][1] + bv.y);
            *(float2*)&C[(size_t)(row + 8) * N + col] =
                make_float2(acc[mi][ni][2] + bv.x, acc[mi][ni][3] + bv.y);
        }
    }
}

// ---------------------------------------------------------------------------
// RoPE (in-place on fp32 qkv)
// ---------------------------------------------------------------------------
__global__ void rope_kernel(float* __restrict__ qkv)
{
    int idx = blockIdx.x * blockDim.x + threadIdx.x;
    const int total = B_ * S_ * 2 * H_ * (RD_ / 2);
    if (idx >= total) return;
    const int i    = idx & 15;  idx >>= 4;
    const int h    = idx & 31;  idx >>= 5;
    const int part = idx & 1;   idx >>= 1;
    const int s    = idx & (S_ - 1); idx >>= 11;
    const int b    = idx;

    const double inv = exp2(-(double)i * (13.287712379549449 / 16.0));
    const float ang  = (float)((double)s * inv);
    const float c  = cosf(ang);
    const float si = sinf(ang);

    const size_t base = ((size_t)(b * S_ + s)) * QKV_N + (size_t)part * D_ + h * HD_;
    const float t1 = qkv[base + i];
    const float t2 = qkv[base + 16 + i];
    qkv[base + i]      = t1 * c  - t2 * si;
    qkv[base + 16 + i] = t1 * si + t2 * c;
}

// ---------------------------------------------------------------------------
// Causal flash attention, HMMA bf16x3, pre-split head-major inputs.
// CTA: 128 q rows x one (b,h); 8 warps x 16 rows; 64-key tiles,
// double-buffered cp.async. Epilogue writes ctx directly as bf16 hi/lo.
// smem stage = Kh,Kl,Vh,Vl each 64x88 bf16 (11264B): 45056B; x2 = 90112B.
// ---------------------------------------------------------------------------
constexpr int ATTN_SMEM = 2 * 45056;   // 90112

__global__ __launch_bounds__(256, 1)
void attn_tc(const __nv_bfloat16* __restrict__ qh_g, const __nv_bfloat16* __restrict__ ql_g,
             const __nv_bfloat16* __restrict__ kh_g, const __nv_bfloat16* __restrict__ kl_g,
             const __nv_bfloat16* __restrict__ vh_g, const __nv_bfloat16* __restrict__ vl_g,
             __nv_bfloat16* __restrict__ chi, __nv_bfloat16* __restrict__ clo)
{
    extern __shared__ __align__(1024) char smc[];
    const uint32_t sb = smem_u32(smc);
    const int qt   = gridDim.x - 1 - blockIdx.x;   // big tiles first
    const int h    = blockIdx.y;
    const int b    = blockIdx.z;
    const int tid  = threadIdx.x;
    const int lane = tid & 31;
    const int wid  = tid >> 5;
    const int wm   = wid * 16;
    const int lr   = lane & 7;
    const int g    = lane >> 3;
    const float scale = 0.11180339887498949f;   // 1/sqrt(80)

    const size_t hb = ((size_t)(b * H_ + h)) * S_ * HD_;

    // ---- stage Q (hi at byte 0, lo at byte 22528) and load fragments ----
    for (int t = tid; t < 2560; t += 256) {
        const int arr = t / 1280, rem = t % 1280;
        const int row = rem / 10, c = rem % 10;
        const __nv_bfloat16* src = (arr ? ql_g : qh_g) + hb
                                   + (size_t)(qt * 128 + row) * HD_ + c * 8;
        cp_async16(sb + (uint32_t)(arr * 22528 + row * 176 + c * 16), src);
    }
    CP_COMMIT();
    asm volatile("cp.async.wait_group 0;" ::: "memory");
    __syncthreads();

    uint32_t qh[5][4], ql[5][4];
    #pragma unroll
    for (int ks = 0; ks < 5; ++ks) {
        const uint32_t ro = (uint32_t)((wm + lr + (g & 1) * 8) * 176 + ks * 32 + (g >> 1) * 16);
        ldsm4u(qh[ks], sb + ro);
        ldsm4u(ql[ks], sb + 22528 + ro);
    }
    __syncthreads();   // Q frags in regs before stage-0 overwrite

    // KV stage loader: byte layout KH 0 / KL 11264 / VH 22528 / VL 33792
    auto load_kv = [&](int kt) {
        const uint32_t st = sb + (uint32_t)(kt & 1) * 45056;
        const __nv_bfloat16* srcs[4] = { kh_g, kl_g, vh_g, vl_g };
        #pragma unroll
        for (int it = 0; it < 10; ++it) {
            const int t = tid + it * 256;            // 0..2559
            const int arr = t / 640, rem = t % 640;
            const int row = rem / 10, c = rem % 10;
            const __nv_bfloat16* src = srcs[arr] + hb
                                       + (size_t)(kt * 64 + row) * HD_ + c * 8;
            cp_async16(st + (uint32_t)(arr * 11264 + row * 176 + c * 16), src);
        }
        CP_COMMIT();
    };

    float o[10][4] = {};
    float mx0 = -1e30f, mx1 = -1e30f, l0 = 0.f, l1 = 0.f;
    const int nkt = 2 * qt + 2;

    load_kv(0);

    for (int kt = 0; kt < nkt; ++kt) {
        if (kt + 1 < nkt) {
            load_kv(kt + 1);
            asm volatile("cp.async.wait_group 1;" ::: "memory");
        } else {
            asm volatile("cp.async.wait_group 0;" ::: "memory");
        }
        __syncthreads();

        const bool active = (qt * 128 + wm + 15 >= kt * 64);
        if (active) {
            const uint32_t st = sb + (uint32_t)(kt & 1) * 45056;

            // ---- scores S = Q K^T (bf16x3) ----
            float s[8][4];
            #pragma unroll
            for (int nb = 0; nb < 8; ++nb) {
                s[nb][0] = s[nb][1] = s[nb][2] = s[nb][3] = 0.f;
                #pragma unroll
                for (int ks = 0; ks < 5; ++ks) {
                    const uint32_t ro = (uint32_t)((nb * 8 + lr) * 176 + ks * 32 + (g & 1) * 16);
                    uint32_t kh0, kh1, kl0, kl1;
                    ldsm2u(kh0, kh1, st + ro);
                    ldsm2u(kl0, kl1, st + 11264 + ro);
                    mma16816(s[nb], qh[ks], kh0, kh1);
                    mma16816(s[nb], qh[ks], kl0, kl1);
                    mma16816(s[nb], ql[ks], kh0, kh1);
                }
                #pragma unroll
                for (int j = 0; j < 4; ++j) s[nb][j] *= scale;
                if (kt >= 2 * qt) {   // diagonal-region mask
                    const int r0 = qt * 128 + wm + (lane >> 2);
                    const int c0 = kt * 64 + nb * 8 + (lane & 3) * 2;
                    if (c0     > r0)     s[nb][0] = -1e30f;
                    if (c0 + 1 > r0)     s[nb][1] = -1e30f;
                    if (c0     > r0 + 8) s[nb][2] = -1e30f;
                    if (c0 + 1 > r0 + 8) s[nb][3] = -1e30f;
                }
            }

            // ---- online softmax ----
            float m0 = -1e30f, m1 = -1e30f;
            #pragma unroll
            for (int nb = 0; nb < 8; ++nb) {
                m0 = fmaxf(m0, fmaxf(s[nb][0], s[nb][1]));
                m1 = fmaxf(m1, fmaxf(s[nb][2], s[nb][3]));
            }
            m0 = fmaxf(m0, __shfl_xor_sync(0xffffffffu, m0, 1));
            m0 = fmaxf(m0, __shfl_xor_sync(0xffffffffu, m0, 2));
            m1 = fmaxf(m1, __shfl_xor_sync(0xffffffffu, m1, 1));
            m1 = fmaxf(m1, __shfl_xor_sync(0xffffffffu, m1, 2));
            const float mn0 = fmaxf(mx0, m0), mn1 = fmaxf(mx1, m1);
            const float corr0 = __expf(mx0 - mn0), corr1 = __expf(mx1 - mn1);
            mx0 = mn0; mx1 = mn1;
            float sum0 = 0.f, sum1 = 0.f;
            #pragma unroll
            for (int nb = 0; nb < 8; ++nb) {
                s[nb][0] = __expf(s[nb][0] - mn0);
                s[nb][1] = __expf(s[nb][1] - mn0);
                s[nb][2] = __expf(s[nb][2] - mn1);
                s[nb][3] = __expf(s[nb][3] - mn1);
                sum0 += s[nb][0] + s[nb][1];
                sum1 += s[nb][2] + s[nb][3];
            }
            sum0 += __shfl_xor_sync(0xffffffffu, sum0, 1);
            sum0 += __shfl_xor_sync(0xffffffffu, sum0, 2);
            sum1 += __shfl_xor_sync(0xffffffffu, sum1, 1);
            sum1 += __shfl_xor_sync(0xffffffffu, sum1, 2);
            l0 = l0 * corr0 + sum0;
            l1 = l1 * corr1 + sum1;
            #pragma unroll
            for (int nd = 0; nd < 10; ++nd) {
                o[nd][0] *= corr0; o[nd][1] *= corr0;
                o[nd][2] *= corr1; o[nd][3] *= corr1;
            }

            // ---- P -> bf16 hi/lo fragments ----
            uint32_t ph[4][4], pl[4][4];
            #pragma unroll
            for (int kb = 0; kb < 4; ++kb) {
                split2(s[2 * kb][0],     s[2 * kb][1],     ph[kb][0], pl[kb][0]);
                split2(s[2 * kb][2],     s[2 * kb][3],     ph[kb][1], pl[kb][1]);
                split2(s[2 * kb + 1][0], s[2 * kb + 1][1], ph[kb][2], pl[kb][2]);
                split2(s[2 * kb + 1][2], s[2 * kb + 1][3], ph[kb][3], pl[kb][3]);
            }

            // ---- O += P V (bf16x3), V via ldmatrix.trans ----
            #pragma unroll
            for (int nd = 0; nd < 10; ++nd) {
                #pragma unroll
                for (int kb = 0; kb < 4; ++kb) {
                    const uint32_t ro = (uint32_t)((kb * 16 + (g & 1) * 8 + lr) * 176 + nd * 16);
                    uint32_t vh0, vh1, vl0, vl1;
                    ldsm2t(vh0, vh1, st + 22528 + ro);
                    ldsm2t(vl0, vl1, st + 33792 + ro);
                    mma16816(o[nd], ph[kb], vh0, vh1);
                    mma16816(o[nd], ph[kb], vl0, vl1);
                    mma16816(o[nd], pl[kb], vh0, vh1);
                }
            }
        }
        __syncthreads();
    }

    // Epilogue: normalize + write ctx directly as bf16 hi/lo (row-major [s][D])
    const float inv0 = 1.f / l0, inv1 = 1.f / l1;
    const int r0 = qt * 128 + wm + (lane >> 2);
    #pragma unroll
    for (int nd = 0; nd < 10; ++nd) {
        const int col = h * HD_ + nd * 8 + (lane & 3) * 2;
        uint32_t hi, lo;
        split2(o[nd][0] * inv0, o[nd][1] * inv0, hi, lo);
        *(uint32_t*)&chi[((size_t)(b * S_ + r0)) * D_ + col] = hi;
        *(uint32_t*)&clo[((size_t)(b * S_ + r0)) * D_ + col] = lo;
        split2(o[nd][2] * inv1, o[nd][3] * inv1, hi, lo);
        *(uint32_t*)&chi[((size_t)(b * S_ + r0 + 8)) * D_ + col] = hi;
        *(uint32_t*)&clo[((size_t)(b * S_ + r0 + 8)) * D_ + col] = lo;
    }
}

// ---------------------------------------------------------------------------
// Launch
// ---------------------------------------------------------------------------
extern "C" void kernel_launch(void* const* d_in, const int* in_sizes, int n_in,
                              void* d_out, int out_size)
{
    const float* x      = (const float*)d_in[0];
    const float* wqkv_w = (const float*)d_in[1];
    const float* wqkv_b = (const float*)d_in[2];
    const float* out_w  = (const float*)d_in[3];
    const float* out_b  = (const float*)d_in[4];
    float* out = (float*)d_out;

    float* qkv;
    __nv_bfloat16 *ahi, *alo, *whi, *wlo, *ohi, *olo;
    __nv_bfloat16 *qh, *ql, *kh, *kl, *vh, *vl;
    cudaGetSymbolAddress((void**)&qkv, g_qkv);
    cudaGetSymbolAddress((void**)&ahi, g_ahi);
    cudaGetSymbolAddress((void**)&alo, g_alo);
    cudaGetSymbolAddress((void**)&whi, g_whi);
    cudaGetSymbolAddress((void**)&wlo, g_wlo);
    cudaGetSymbolAddress((void**)&ohi, g_ohi);
    cudaGetSymbolAddress((void**)&olo, g_olo);
    cudaGetSymbolAddress((void**)&qh, g_qh);
    cudaGetSymbolAddress((void**)&ql, g_ql);
    cudaGetSymbolAddress((void**)&kh, g_kh);
    cudaGetSymbolAddress((void**)&kl, g_kl);
    cudaGetSymbolAddress((void**)&vh, g_vh);
    cudaGetSymbolAddress((void**)&vl, g_vl);

    cudaFuncSetAttribute(gemm_hmma,
                         cudaFuncAttributeMaxDynamicSharedMemorySize, GEMM_SMEM);
    cudaFuncSetAttribute(attn_tc,
                         cudaFuncAttributeMaxDynamicSharedMemorySize, ATTN_SMEM);

    // 0) split x / weights into bf16 hi/lo
    {
        const int n4x = M_ROWS * D_ / 4;
        cvt_split<<<n4x / 256, 256>>>((const float4*)x, (uint2*)ahi, (uint2*)alo, n4x);
        const int n4w = QKV_N * D_ / 4;
        cvt_split<<<n4w / 256, 256>>>((const float4*)wqkv_w, (uint2*)whi, (uint2*)wlo, n4w);
        const int n4o = D_ * D_ / 4;
        cvt_split<<<n4o / 256, 256>>>((const float4*)out_w, (uint2*)ohi, (uint2*)olo, n4o);
    }

    // 1) QKV = X @ Wqkv^T + b
    dim3 g1(QKV_N / 128, M_ROWS / 128);
    gemm_hmma<<<g1, 256, GEMM_SMEM>>>(ahi, alo, whi, wlo, wqkv_b, qkv,
                                      M_ROWS, QKV_N, D_);

    // 2) RoPE on q,k (fp32)
    const int rope_total = B_ * S_ * 2 * H_ * (RD_ / 2);
    rope_kernel<<<rope_total / 256, 256>>>(qkv);

    // 3) split qkv -> head-major bf16 hi/lo
    cvt_qkv<<<(M_ROWS * QKV_N / 4) / 256, 256>>>((const float4*)qkv);

    // 4) causal attention -> ctx (written directly as hi/lo into ahi/alo)
    dim3 ga(S_ / 128, H_, B_);
    attn_tc<<<ga, 256, ATTN_SMEM>>>(qh, ql, kh, kl, vh, vl, ahi, alo);

    // 5) out = ctx @ Wout^T + b
    dim3 g2(D_ / 128, M_ROWS / 128);
    gemm_hmma<<<g2, 256, GEMM_SMEM>>>(ahi, alo, ohi, olo, out_b, out,
                                      M_ROWS, D_, D_);
}